// round 1
// baseline (speedup 1.0000x reference)
#include <cuda_runtime.h>
#include <cstdint>

#define RANK  200
#define NNZ   500000
#define N_ENT 200000
#define N_REL 500
#define RV4   (RANK / 4)   // 50 float4 per row

// Scratch (static __device__ globals — no allocation allowed in kernel_launch).
__device__ float g_deriv[NNZ];     // 2 * (kruskal - val) per nnz
__device__ int   g_win_a[N_ENT];   // winner key per entity row: n (subj) or n+NNZ (obj), -1 = none
__device__ int   g_win_b[N_REL];   // winner key per relation row: n, -1 = none

// ---------------------------------------------------------------------------
// Pass 0: reset winner arrays.
// ---------------------------------------------------------------------------
__global__ void init_win_kernel() {
    int i = blockIdx.x * blockDim.x + threadIdx.x;
    if (i < N_ENT) g_win_a[i] = -1;
    if (i < N_REL) g_win_b[i] = -1;
}

// ---------------------------------------------------------------------------
// Pass A: one warp per nnz. Gather a0/b1/a2, rank-200 dot via warp reduction,
// emit loss + deriv, and race the scatter-overwrite winners with atomicMax.
// Key encoding reproduces XLA sequential-scatter semantics:
//   grad_a: obj writes (.set applied second) beat subj writes -> key n+NNZ vs n,
//   within a class, higher nnz index wins (last update wins).
// ---------------------------------------------------------------------------
__global__ void __launch_bounds__(256) pass_a_kernel(
    const int*   __restrict__ coo,
    const float* __restrict__ vals,
    const float* __restrict__ a,
    const float* __restrict__ b,
    float*       __restrict__ loss)
{
    int warp = (blockIdx.x * blockDim.x + threadIdx.x) >> 5;
    int lane = threadIdx.x & 31;
    if (warp >= NNZ) return;

    int s = coo[3 * warp + 0];
    int r = coo[3 * warp + 1];
    int o = coo[3 * warp + 2];

    const float4* a0 = (const float4*)(a + (size_t)s * RANK);
    const float4* b1 = (const float4*)(b + (size_t)r * RANK);
    const float4* a2 = (const float4*)(a + (size_t)o * RANK);

    float sum = 0.0f;
    for (int j = lane; j < RV4; j += 32) {
        float4 x = __ldg(a0 + j);
        float4 y = __ldg(b1 + j);
        float4 z = __ldg(a2 + j);
        sum += x.x * y.x * z.x;
        sum += x.y * y.y * z.y;
        sum += x.z * y.z * z.z;
        sum += x.w * y.w * z.w;
    }
    #pragma unroll
    for (int off = 16; off; off >>= 1)
        sum += __shfl_down_sync(0xffffffffu, sum, off);

    if (lane == 0) {
        float diff = sum - vals[warp];
        loss[warp]    = diff * diff;
        g_deriv[warp] = 2.0f * diff;
        atomicMax(&g_win_a[s], warp);        // subj class
        atomicMax(&g_win_a[o], warp + NNZ);  // obj class (always beats subj)
        atomicMax(&g_win_b[r], warp);
    }
}

// ---------------------------------------------------------------------------
// Pass B-a: one warp per entity row. Losers get zeros (this also initializes
// the poisoned output). Winner rows re-gather the two needed embedding rows
// and write d * x * y.
//   subj winner (key <  NNZ): g_a = deriv * b1 * a2
//   obj  winner (key >= NNZ): g_c = deriv * a0 * b1
// ---------------------------------------------------------------------------
__global__ void __launch_bounds__(256) pass_ba_kernel(
    const int*   __restrict__ coo,
    const float* __restrict__ a,
    const float* __restrict__ b,
    float*       __restrict__ grad_a)
{
    int warp = (blockIdx.x * blockDim.x + threadIdx.x) >> 5;
    int lane = threadIdx.x & 31;
    if (warp >= N_ENT) return;

    float4* out = (float4*)(grad_a + (size_t)warp * RANK);
    int k = g_win_a[warp];

    if (k < 0) {
        float4 z = make_float4(0.f, 0.f, 0.f, 0.f);
        for (int j = lane; j < RV4; j += 32) out[j] = z;
        return;
    }

    bool is_obj = (k >= NNZ);
    int  n      = is_obj ? (k - NNZ) : k;

    int s = coo[3 * n + 0];
    int r = coo[3 * n + 1];
    int o = coo[3 * n + 2];
    float d = g_deriv[n];

    const float4* x;
    const float4* y;
    if (is_obj) {            // g_c = d * a0 * b1
        x = (const float4*)(a + (size_t)s * RANK);
        y = (const float4*)(b + (size_t)r * RANK);
    } else {                 // g_a = d * b1 * a2
        x = (const float4*)(b + (size_t)r * RANK);
        y = (const float4*)(a + (size_t)o * RANK);
    }

    for (int j = lane; j < RV4; j += 32) {
        float4 u = __ldg(x + j);
        float4 v = __ldg(y + j);
        out[j] = make_float4(d * u.x * v.x, d * u.y * v.y,
                             d * u.z * v.z, d * u.w * v.w);
    }
}

// ---------------------------------------------------------------------------
// Pass B-b: one warp per relation row.  g_b = deriv * a0 * a2 for the winner.
// ---------------------------------------------------------------------------
__global__ void __launch_bounds__(256) pass_bb_kernel(
    const int*   __restrict__ coo,
    const float* __restrict__ a,
    float*       __restrict__ grad_b)
{
    int warp = (blockIdx.x * blockDim.x + threadIdx.x) >> 5;
    int lane = threadIdx.x & 31;
    if (warp >= N_REL) return;

    float4* out = (float4*)(grad_b + (size_t)warp * RANK);
    int k = g_win_b[warp];

    if (k < 0) {
        float4 z = make_float4(0.f, 0.f, 0.f, 0.f);
        for (int j = lane; j < RV4; j += 32) out[j] = z;
        return;
    }

    int s = coo[3 * k + 0];
    int o = coo[3 * k + 2];
    float d = g_deriv[k];

    const float4* x = (const float4*)(a + (size_t)s * RANK);
    const float4* y = (const float4*)(a + (size_t)o * RANK);

    for (int j = lane; j < RV4; j += 32) {
        float4 u = __ldg(x + j);
        float4 v = __ldg(y + j);
        out[j] = make_float4(d * u.x * v.x, d * u.y * v.y,
                             d * u.z * v.z, d * u.w * v.w);
    }
}

// ---------------------------------------------------------------------------
// Launch. Inputs (metadata order): coo_ns int32 [NNZ,3], vals_ns f32 [NNZ],
// a f32 [N_ENT,RANK], b f32 [N_REL,RANK].
// Output: loss[NNZ] | grad_a[N_ENT*RANK] | grad_b[N_REL*RANK]  (f32).
// ---------------------------------------------------------------------------
extern "C" void kernel_launch(void* const* d_in, const int* in_sizes, int n_in,
                              void* d_out, int out_size)
{
    const int*   coo  = (const int*)d_in[0];
    const float* vals = (const float*)d_in[1];
    const float* a    = (const float*)d_in[2];
    const float* b    = (const float*)d_in[3];

    float* out    = (float*)d_out;
    float* loss   = out;
    float* grad_a = out + NNZ;
    float* grad_b = out + NNZ + (size_t)N_ENT * RANK;

    init_win_kernel<<<(N_ENT + 255) / 256, 256>>>();

    {   // one warp per nnz
        long long threads = (long long)NNZ * 32;
        int blocks = (int)((threads + 255) / 256);
        pass_a_kernel<<<blocks, 256>>>(coo, vals, a, b, loss);
    }
    {   // one warp per entity row
        long long threads = (long long)N_ENT * 32;
        int blocks = (int)((threads + 255) / 256);
        pass_ba_kernel<<<blocks, 256>>>(coo, a, b, grad_a);
    }
    {   // one warp per relation row
        int blocks = (N_REL * 32 + 255) / 256;
        pass_bb_kernel<<<blocks, 256>>>(coo, a, grad_b);
    }
}

// round 2
// speedup vs baseline: 1.0362x; 1.0362x over previous
#include <cuda_runtime.h>
#include <cstdint>

#define RANK  200
#define NNZ   500000
#define N_ENT 200000
#define N_REL 500
#define RV4   (RANK / 4)   // 50 float4 per row

// Scratch (__device__ globals: zero-initialized by CUDA at module load; the
// pass_b kernel self-resets winner slots to 0 after consuming them so every
// invocation — correctness run and each graph replay — starts identically).
__device__ float g_deriv[NNZ];     // 2 * (kruskal - val) per nnz
__device__ int   g_win_a[N_ENT];   // winner key: n+1 (subj) or n+1+NNZ (obj); 0 = none
__device__ int   g_win_b[N_REL];   // winner key: n+1; 0 = none

// ---------------------------------------------------------------------------
// Pass A: one warp per nnz. Gather a0/b1/a2, rank-200 dot via warp reduction,
// emit loss + deriv, and race the scatter-overwrite winners with atomicMax.
// Key encoding reproduces XLA sequential-scatter semantics:
//   grad_a: obj writes (.set applied second) beat subj writes -> key n+1+NNZ
//   vs n+1; within a class, higher nnz index wins (last update wins).
// ---------------------------------------------------------------------------
__global__ void __launch_bounds__(256) pass_a_kernel(
    const int*   __restrict__ coo,
    const float* __restrict__ vals,
    const float* __restrict__ a,
    const float* __restrict__ b,
    float*       __restrict__ loss)
{
    int warp = (blockIdx.x * blockDim.x + threadIdx.x) >> 5;
    int lane = threadIdx.x & 31;
    if (warp >= NNZ) return;

    int s = coo[3 * warp + 0];
    int r = coo[3 * warp + 1];
    int o = coo[3 * warp + 2];

    const float4* a0 = (const float4*)(a + (size_t)s * RANK);
    const float4* b1 = (const float4*)(b + (size_t)r * RANK);
    const float4* a2 = (const float4*)(a + (size_t)o * RANK);

    float sum = 0.0f;
    #pragma unroll
    for (int it = 0; it < 2; it++) {
        int j = lane + it * 32;
        if (j < RV4) {
            float4 x = __ldg(a0 + j);
            float4 y = __ldg(b1 + j);
            float4 z = __ldg(a2 + j);
            sum += x.x * y.x * z.x;
            sum += x.y * y.y * z.y;
            sum += x.z * y.z * z.z;
            sum += x.w * y.w * z.w;
        }
    }
    #pragma unroll
    for (int off = 16; off; off >>= 1)
        sum += __shfl_down_sync(0xffffffffu, sum, off);

    if (lane == 0) {
        float diff = sum - __ldg(vals + warp);
        __stcs(loss + warp, diff * diff);       // streaming: never re-read
        g_deriv[warp] = 2.0f * diff;
        atomicMax(&g_win_a[s], warp + 1);       // subj class
        atomicMax(&g_win_a[o], warp + 1 + NNZ); // obj class (beats subj)
        atomicMax(&g_win_b[r], warp + 1);
    }
}

// ---------------------------------------------------------------------------
// Pass B (fused): warps [0, N_ENT) -> grad_a rows, warps [N_ENT, N_ENT+N_REL)
// -> grad_b rows. Loser rows get zeros (doubles as output init). Winner rows
// re-gather the two needed embedding rows and write d * x * y with streaming
// stores (grad output is write-once; keep L2 for the a-table gathers).
// Each warp resets its winner slot to 0 for the next invocation.
// ---------------------------------------------------------------------------
__global__ void __launch_bounds__(256) pass_b_kernel(
    const int*   __restrict__ coo,
    const float* __restrict__ a,
    const float* __restrict__ b,
    float*       __restrict__ grad_a,
    float*       __restrict__ grad_b)
{
    int warp = (blockIdx.x * blockDim.x + threadIdx.x) >> 5;
    int lane = threadIdx.x & 31;
    if (warp >= N_ENT + N_REL) return;

    float4* out;
    const float4* x;
    const float4* y;
    float d = 0.0f;
    bool have = false;

    if (warp < N_ENT) {
        out = (float4*)(grad_a + (size_t)warp * RANK);
        int k = g_win_a[warp];
        if (k > 0) {
            if (lane == 0) g_win_a[warp] = 0;        // self-reset
            bool is_obj = (k > NNZ);
            int  n      = is_obj ? (k - 1 - NNZ) : (k - 1);
            int s = coo[3 * n + 0];
            int r = coo[3 * n + 1];
            int o = coo[3 * n + 2];
            d = g_deriv[n];
            if (is_obj) {        // g_c = d * a0 * b1
                x = (const float4*)(a + (size_t)s * RANK);
                y = (const float4*)(b + (size_t)r * RANK);
            } else {             // g_a = d * b1 * a2
                x = (const float4*)(b + (size_t)r * RANK);
                y = (const float4*)(a + (size_t)o * RANK);
            }
            have = true;
        }
    } else {
        int row = warp - N_ENT;
        out = (float4*)(grad_b + (size_t)row * RANK);
        int k = g_win_b[row];
        if (k > 0) {
            if (lane == 0) g_win_b[row] = 0;         // self-reset
            int n = k - 1;
            int s = coo[3 * n + 0];
            int o = coo[3 * n + 2];
            d = g_deriv[n];
            x = (const float4*)(a + (size_t)s * RANK);   // g_b = d * a0 * a2
            y = (const float4*)(a + (size_t)o * RANK);
            have = true;
        }
    }

    if (!have) {
        float4 z = make_float4(0.f, 0.f, 0.f, 0.f);
        #pragma unroll
        for (int it = 0; it < 2; it++) {
            int j = lane + it * 32;
            if (j < RV4) __stcs(out + j, z);
        }
        return;
    }

    #pragma unroll
    for (int it = 0; it < 2; it++) {
        int j = lane + it * 32;
        if (j < RV4) {
            float4 u = __ldg(x + j);
            float4 v = __ldg(y + j);
            float4 w = make_float4(d * u.x * v.x, d * u.y * v.y,
                                   d * u.z * v.z, d * u.w * v.w);
            __stcs(out + j, w);
        }
    }
}

// ---------------------------------------------------------------------------
// Launch. Inputs (metadata order): coo_ns int32 [NNZ,3], vals_ns f32 [NNZ],
// a f32 [N_ENT,RANK], b f32 [N_REL,RANK].
// Output: loss[NNZ] | grad_a[N_ENT*RANK] | grad_b[N_REL*RANK]  (f32).
// ---------------------------------------------------------------------------
extern "C" void kernel_launch(void* const* d_in, const int* in_sizes, int n_in,
                              void* d_out, int out_size)
{
    const int*   coo  = (const int*)d_in[0];
    const float* vals = (const float*)d_in[1];
    const float* a    = (const float*)d_in[2];
    const float* b    = (const float*)d_in[3];

    float* out    = (float*)d_out;
    float* loss   = out;
    float* grad_a = out + NNZ;
    float* grad_b = out + NNZ + (size_t)N_ENT * RANK;

    {   // one warp per nnz
        long long threads = (long long)NNZ * 32;
        int blocks = (int)((threads + 255) / 256);
        pass_a_kernel<<<blocks, 256>>>(coo, vals, a, b, loss);
    }
    {   // one warp per output row (entity rows then relation rows)
        long long threads = (long long)(N_ENT + N_REL) * 32;
        int blocks = (int)((threads + 255) / 256);
        pass_b_kernel<<<blocks, 256>>>(coo, a, b, grad_a, grad_b);
    }
}